// round 16
// baseline (speedup 1.0000x reference)
#include <cuda_runtime.h>
#include <cuda_fp16.h>
#include <math.h>
#include <cstdint>

#define B_   4
#define N_   2048
#define D_   512
#define H_   8
#define DH   64
#define DQ2  128          // concatenated head dim: [q | q_met]
#define BHn  (B_*H_)      // 32
#define ROWS (B_*N_)      // 8192
#define SCALE 0.125f      // 64^-0.5

// Scratch (device globals — no allocations allowed)
__device__ __half g_Q2h[BHn * N_ * DQ2];        // 16 MB [(bh), n, 128]
__device__ __half g_K2h[BHn * N_ * DQ2];        // 16 MB
__device__ __half g_Vth[BHn * DH * N_];         //  8 MB [(bh), d, n]
__device__ float  g_OH [ROWS * D_];             // 16 MB (b, n, h*64+d)
__device__ __half g_Ph [(long)BHn * N_ * N_];   // 268 MB unnormalized exp(sim)
__device__ float  g_RS [BHn * N_];              // 256 KB  1/rowsum

// ===========================================================================
// helpers
// ===========================================================================
__device__ __forceinline__ float tf32r(float x) {
    uint32_t u = __float_as_uint(x);
    asm("cvt.rn.tf32.f32 %0, %1;" : "=r"(u) : "r"(u));
    return __uint_as_float(u);
}
__device__ __forceinline__ uint32_t h2u(float a, float b) {
    __half2 h = __floats2half2_rn(a, b);
    return *(uint32_t*)&h;
}
__device__ __forceinline__ void mma8(float c[4], const uint32_t a[4], const uint32_t b[2]) {
    asm volatile(
        "mma.sync.aligned.m16n8k8.row.col.f32.tf32.tf32.f32 "
        "{%0,%1,%2,%3}, {%4,%5,%6,%7}, {%8,%9}, {%0,%1,%2,%3};"
        : "+f"(c[0]), "+f"(c[1]), "+f"(c[2]), "+f"(c[3])
        : "r"(a[0]), "r"(a[1]), "r"(a[2]), "r"(a[3]), "r"(b[0]), "r"(b[1]));
}
__device__ __forceinline__ void mma16(float c[4], const uint32_t a[4], const uint32_t b[2]) {
    asm volatile(
        "mma.sync.aligned.m16n8k16.row.col.f32.f16.f16.f32 "
        "{%0,%1,%2,%3}, {%4,%5,%6,%7}, {%8,%9}, {%0,%1,%2,%3};"
        : "+f"(c[0]), "+f"(c[1]), "+f"(c[2]), "+f"(c[3])
        : "r"(a[0]), "r"(a[1]), "r"(a[2]), "r"(a[3]), "r"(b[0]), "r"(b[1]));
}

// ===========================================================================
// Kernel 1: proj via mma.sync tf32; epilogue writes fp16 head-split tensors.
// (R13 verbatim)
// ===========================================================================
#define APAD 44
#define BPAD 136
#define PROJ_SMEM ((2*128*APAD + 2*32*BPAD) * 4)   // 79872 B

__global__ __launch_bounds__(256) void proj_mma(
    const float* __restrict__ x, const float* __restrict__ met,
    const float* __restrict__ yz, const float* __restrict__ Wq,
    const float* __restrict__ Wk, const float* __restrict__ Wv)
{
    extern __shared__ float smf[];
    float* As = smf;                    // 2 x [128][APAD]
    float* Bs = smf + 2*128*APAD;       // 2 x [32][BPAD]

    const int mode = blockIdx.z;
    const float* A = (mode == 0) ? x : (mode == 1 || mode == 3) ? met : yz;
    const float* W = (mode < 2) ? Wq : (mode < 4) ? Wk : Wv;

    const int tid = threadIdx.x, lane = tid & 31, wid = tid >> 5;
    const int wm = wid >> 1, wn = wid & 1;
    const int row0 = blockIdx.y * 128;
    const int col0 = blockIdx.x * 128;

    float4 ta[4]; float tb[16];
    auto loadA = [&](int k0) {
        #pragma unroll
        for (int q = 0; q < 4; q++) {
            int e = tid + q * 256;
            int r = e >> 3, kg = e & 7;
            ta[q] = *(const float4*)&A[(long)(row0 + r) * D_ + k0 + kg * 4];
        }
    };
    auto loadB = [&](int k0) {
        #pragma unroll
        for (int j = 0; j < 16; j++) {
            int i = tid + j * 256;
            int k = i >> 7, n = i & 127;
            tb[j] = W[(long)(k0 + k) * D_ + col0 + n];
        }
    };
    auto stsA = [&](int buf) {
        float* Ab = As + buf * 128 * APAD;
        #pragma unroll
        for (int q = 0; q < 4; q++) {
            int e = tid + q * 256;
            int r = e >> 3, kg = e & 7;
            float4 v = ta[q];
            v.x = tf32r(v.x); v.y = tf32r(v.y); v.z = tf32r(v.z); v.w = tf32r(v.w);
            *(float4*)&Ab[r * APAD + kg * 4] = v;
        }
    };
    auto stsB = [&](int buf) {
        float* Bb = Bs + buf * 32 * BPAD;
        #pragma unroll
        for (int j = 0; j < 16; j++) {
            int i = tid + j * 256;
            int k = i >> 7, n = i & 127;
            Bb[k * BPAD + n] = tf32r(tb[j]);
        }
    };

    float acc[2][8][4] = {};
    loadA(0); loadB(0); stsA(0); stsB(0);
    __syncthreads();

    for (int c = 0; c < 16; c++) {
        if (c + 1 < 16) { loadA((c + 1) * 32); loadB((c + 1) * 32); }
        const int buf = c & 1;
        const float* Ab = As + buf * 128 * APAD;
        const float* Bb = Bs + buf * 32 * BPAD;

        #pragma unroll
        for (int ks = 0; ks < 4; ks++) {
            const int kk = ks * 8 + (lane & 3);
            uint32_t a[2][4], b[8][2];
            #pragma unroll
            for (int ma = 0; ma < 2; ma++) {
                int r = wm * 32 + ma * 16 + (lane >> 2);
                a[ma][0] = __float_as_uint(Ab[r * APAD + kk]);
                a[ma][1] = __float_as_uint(Ab[(r + 8) * APAD + kk]);
                a[ma][2] = __float_as_uint(Ab[r * APAD + kk + 4]);
                a[ma][3] = __float_as_uint(Ab[(r + 8) * APAD + kk + 4]);
            }
            #pragma unroll
            for (int na = 0; na < 8; na++) {
                int n = wn * 64 + na * 8 + (lane >> 2);
                b[na][0] = __float_as_uint(Bb[kk * BPAD + n]);
                b[na][1] = __float_as_uint(Bb[(kk + 4) * BPAD + n]);
            }
            #pragma unroll
            for (int ma = 0; ma < 2; ma++)
                #pragma unroll
                for (int na = 0; na < 8; na++)
                    mma8(acc[ma][na], a[ma], b[na]);
        }
        __syncthreads();
        if (c + 1 < 16) { stsA(buf ^ 1); stsB(buf ^ 1); }
        __syncthreads();
    }

    #pragma unroll
    for (int ma = 0; ma < 2; ma++) {
        #pragma unroll
        for (int half = 0; half < 2; half++) {
            int r = row0 + wm * 32 + ma * 16 + half * 8 + (lane >> 2);
            int bb = r >> 11, n = r & 2047;
            #pragma unroll
            for (int na = 0; na < 8; na++) {
                int cgl = col0 + wn * 64 + na * 8 + (lane & 3) * 2;
                int h = cgl >> 6, d = cgl & 63;
                float p = acc[ma][na][half * 2 + 0];
                float q = acc[ma][na][half * 2 + 1];
                long base = (long)(bb * H_ + h) * N_ + n;
                if (mode == 0)
                    *(__half2*)&g_Q2h[base * DQ2 + d] = __floats2half2_rn(p, q);
                else if (mode == 1)
                    *(__half2*)&g_Q2h[base * DQ2 + d + DH] = __floats2half2_rn(p, q);
                else if (mode == 2)
                    *(__half2*)&g_K2h[base * DQ2 + d] = __floats2half2_rn(p, q);
                else if (mode == 3)
                    *(__half2*)&g_K2h[base * DQ2 + d + DH] = __floats2half2_rn(p, q);
                else {
                    g_Vth[((long)(bb * H_ + h) * DH + d) * N_ + n] = __float2half_rn(p);
                    g_Vth[((long)(bb * H_ + h) * DH + d + 1) * N_ + n] = __float2half_rn(q);
                }
            }
        }
    }
}

// ===========================================================================
// Kernel 2: sim via mma.sync fp16; epilogue writes p~ = exp(S*SCALE) fp16
// to g_Ph and accumulates rowsums -> g_RS.  (R13 verbatim)
// ===========================================================================
#define SIM_SMEM ((8192 + 2*2048 + 128) * 4)   // 49664 B

__global__ __launch_bounds__(256) void sim_f16p(void)
{
    extern __shared__ uint32_t sm[];
    uint32_t* Qs = sm;
    uint32_t* Kb = sm + 8192;
    float* rowsumS = (float*)(sm + 12288);

    const int tid = threadIdx.x, lane = tid & 31, wid = tid >> 5;
    const int wm = wid >> 1, wn = wid & 1;
    const int bh = blockIdx.y, rb = blockIdx.x;
    const __half* Qg = g_Q2h + ((long)bh * N_ + rb * 128) * DQ2;
    const __half* Kg = g_K2h + (long)bh * N_ * DQ2;
    __half* Php = g_Ph + ((long)bh * N_ + rb * 128) * N_;

    for (int e = tid; e < 8192; e += 256) {
        int j = e & 3, l = (e >> 2) & 31, ks = (e >> 7) & 7;
        int ma = (e >> 10) & 1, qm = (e >> 11) & 3;
        int r = qm * 32 + ma * 16 + (l >> 2) + (j & 1) * 8;
        int k = ks * 16 + (l & 3) * 2 + (j >> 1) * 8;
        Qs[e] = *(const uint32_t*)&Qg[(long)r * DQ2 + k];
    }
    if (tid < 128) rowsumS[tid] = 0.f;

    uint4 tk[2];
    auto loadK = [&](int it) {
        int ct = it >> 2, kc = it & 3;
        const __half* src = Kg + (long)(ct * 128) * DQ2 + kc * 32;
        #pragma unroll
        for (int q = 0; q < 2; q++) {
            int e = tid + q * 256;
            int col = e >> 2, kq = e & 3;
            tk[q] = *(const uint4*)(src + (long)col * DQ2 + kq * 8);
        }
    };
    auto storeK = [&](int buf) {
        uint32_t* Bb = Kb + buf * 2048;
        #pragma unroll
        for (int q = 0; q < 2; q++) {
            int e = tid + q * 256;
            int col = e >> 2, kq = e & 3;
            int wn_ = col >> 6, na = (col >> 3) & 7;
            int cb2 = (col >> 2) & 1;
            uint32_t w4[4] = { tk[q].x, tk[q].y, tk[q].z, tk[q].w };
            #pragma unroll
            for (int w = 0; w < 4; w++) {
                int k2 = kq * 8 + w * 2;
                int ks = k2 >> 4, kk2 = k2 & 15;
                int lt = ((col & 7) << 2) | ((kk2 >> 1) & 3);
                int reg = kk2 >> 3;
                int idx = ((((wn_ * 8 + na) * 2 + ks) * 32) + lt) * 2 + reg;
                idx ^= (ks << 1) ^ (cb2 << 2);
                Bb[idx] = w4[w];
            }
        }
    };

    float rs[2][2] = {};
    float acc[2][8][4];
    loadK(0); storeK(0);
    __syncthreads();

    const int ldxor = (((lane >> 4) & 1) << 2);
    for (int it = 0; it < 64; it++) {
        const int kc = it & 3, buf = it & 1;
        if (kc == 0) {
            #pragma unroll
            for (int i = 0; i < 2; i++)
                #pragma unroll
                for (int j = 0; j < 8; j++)
                    #pragma unroll
                    for (int t = 0; t < 4; t++) acc[i][j][t] = 0.f;
        }
        if (it + 1 < 64) loadK(it + 1);

        const uint32_t* Bb = Kb + buf * 2048;
        #pragma unroll
        for (int ks = 0; ks < 2; ks++) {
            int ksG = kc * 2 + ks;
            uint32_t a[2][4], b[8][2];
            *(uint4*)a[0] = *(const uint4*)&Qs[(((wm * 2 + 0) * 8 + ksG) * 32 + lane) * 4];
            *(uint4*)a[1] = *(const uint4*)&Qs[(((wm * 2 + 1) * 8 + ksG) * 32 + lane) * 4];
            #pragma unroll
            for (int na = 0; na < 8; na++) {
                int widx = ((((wn * 8 + na) * 2 + ks) * 32 + lane) * 2) ^ (ks << 1) ^ ldxor;
                *(uint2*)b[na] = *(const uint2*)&Bb[widx];
            }
            #pragma unroll
            for (int ma = 0; ma < 2; ma++)
                #pragma unroll
                for (int na = 0; na < 8; na++)
                    mma16(acc[ma][na], a[ma], b[na]);
        }

        if (kc == 3) {
            int ct = it >> 2;
            #pragma unroll
            for (int ma = 0; ma < 2; ma++) {
                int row = wm * 32 + ma * 16 + (lane >> 2);
                #pragma unroll
                for (int na = 0; na < 8; na++) {
                    float p0 = __expf(acc[ma][na][0] * SCALE);
                    float p1 = __expf(acc[ma][na][1] * SCALE);
                    float p2 = __expf(acc[ma][na][2] * SCALE);
                    float p3 = __expf(acc[ma][na][3] * SCALE);
                    rs[ma][0] += p0 + p1;
                    rs[ma][1] += p2 + p3;
                    int col = ct * 128 + wn * 64 + na * 8 + (lane & 3) * 2;
                    *(uint32_t*)&Php[(long)row * N_ + col]       = h2u(p0, p1);
                    *(uint32_t*)&Php[(long)(row + 8) * N_ + col] = h2u(p2, p3);
                }
            }
        }
        if (it + 1 < 64) storeK(buf ^ 1);
        __syncthreads();
    }

    #pragma unroll
    for (int ma = 0; ma < 2; ma++)
        #pragma unroll
        for (int hf = 0; hf < 2; hf++) {
            float v = rs[ma][hf];
            v += __shfl_xor_sync(0xffffffffu, v, 1);
            v += __shfl_xor_sync(0xffffffffu, v, 2);
            if ((lane & 3) == 0)
                atomicAdd(&rowsumS[wm * 32 + ma * 16 + hf * 8 + (lane >> 2)], v);
        }
    __syncthreads();
    if (tid < 128)
        g_RS[bh * N_ + rb * 128 + tid] = 1.0f / rowsumS[tid];
}

// ===========================================================================
// Kernel 3: normalize — attn = float(p~) * (1/rowsum).  (R13 verbatim)
// ===========================================================================
__global__ __launch_bounds__(256) void norm_kernel(float* __restrict__ attn)
{
    const long row = blockIdx.x;
    const __half* p = g_Ph + row * N_;
    float* o = attn + row * N_;
    const float iv = g_RS[row];
    const int c8 = threadIdx.x * 8;
    uint4 v = *(const uint4*)&p[c8];
    __half2* hp = (__half2*)&v;
    float2 f0 = __half22float2(hp[0]);
    float2 f1 = __half22float2(hp[1]);
    float2 f2 = __half22float2(hp[2]);
    float2 f3 = __half22float2(hp[3]);
    *(float4*)&o[c8]     = make_float4(f0.x * iv, f0.y * iv, f1.x * iv, f1.y * iv);
    *(float4*)&o[c8 + 4] = make_float4(f2.x * iv, f2.y * iv, f3.x * iv, f3.y * iv);
}

// ===========================================================================
// Kernel 4: OutH = attn @ V via fp16 mma; A = p~ * (1/rowsum).  (R13 verbatim)
// ===========================================================================
#define PV_SMEM ((2*2048 + 2*1024 + 128) * 4)   // 25088 B

__global__ __launch_bounds__(256) void pv_tc(void)
{
    extern __shared__ uint32_t sm[];
    uint32_t* Ab = sm;
    uint32_t* Bv = sm + 4096;
    float* sInv = (float*)(sm + 6144);

    const int tid = threadIdx.x, lane = tid & 31, wid = tid >> 5;
    const int wm = wid >> 1, wn = wid & 1;
    const int bh = blockIdx.y, rb = blockIdx.x;
    const __half* Pg = g_Ph + ((long)bh * N_ + rb * 128) * N_;
    const __half* Vg = g_Vth + (long)bh * DH * N_;

    if (tid < 128) sInv[tid] = g_RS[bh * N_ + rb * 128 + tid];
    __syncthreads();

    uint4 tph[2]; uint4 tv;
    auto loadT = [&](int it) {
        #pragma unroll
        for (int q = 0; q < 2; q++) {
            int e = tid + q * 256;
            int row = e >> 2, kq = e & 3;
            tph[q] = *(const uint4*)(Pg + (long)row * N_ + it * 32 + kq * 8);
        }
        {
            int d = tid >> 2, kq = tid & 3;
            tv = *(const uint4*)(Vg + (long)d * N_ + it * 32 + kq * 8);
        }
    };
    auto storeT = [&](int buf) {
        uint32_t* A = Ab + buf * 2048;
        #pragma unroll
        for (int q = 0; q < 2; q++) {
            int e = tid + q * 256;
            int row = e >> 2, kq = e & 3;
            float iv = sInv[row];
            int wm_ = row >> 5, ma = (row >> 4) & 1, rr = row & 15;
            const __half2* hp = (const __half2*)&tph[q];
            #pragma unroll
            for (int w = 0; w < 4; w++) {
                float2 f = __half22float2(hp[w]);
                int k2 = kq * 8 + w * 2;
                int ks = k2 >> 4, kk2 = k2 & 15;
                int lt = ((rr & 7) << 2) | ((kk2 >> 1) & 3);
                int j = (rr >> 3) | ((kk2 >> 3) << 1);
                int idx = (((((wm_ * 2 + ma) * 2 + ks) * 32) + lt) * 4 + j) ^ (ks << 2);
                A[idx] = h2u(f.x * iv, f.y * iv);
            }
        }
        uint32_t* Bt = Bv + buf * 1024;
        {
            int d = tid >> 2, kq = tid & 3;
            int wn_ = d >> 5, na = (d >> 3) & 3;
            int cb2 = (d >> 2) & 1;
            uint32_t w4[4] = { tv.x, tv.y, tv.z, tv.w };
            #pragma unroll
            for (int w = 0; w < 4; w++) {
                int k2 = kq * 8 + w * 2;
                int ks = k2 >> 4, kk2 = k2 & 15;
                int lt = ((d & 7) << 2) | ((kk2 >> 1) & 3);
                int reg = kk2 >> 3;
                int idx = ((((wn_ * 4 + na) * 2 + ks) * 32) + lt) * 2 + reg;
                idx ^= (ks << 1) ^ (cb2 << 2);
                Bt[idx] = w4[w];
            }
        }
    };

    float acc[2][4][4] = {};
    loadT(0); storeT(0);
    __syncthreads();

    const int ldxor = (((lane >> 4) & 1) << 2);
    for (int it = 0; it < 64; it++) {
        const int buf = it & 1;
        if (it + 1 < 64) loadT(it + 1);

        const uint32_t* A = Ab + buf * 2048;
        const uint32_t* Bt = Bv + buf * 1024;
        #pragma unroll
        for (int ks = 0; ks < 2; ks++) {
            uint32_t a[2][4], b[4][2];
            *(uint4*)a[0] = *(const uint4*)&A[((((wm * 2 + 0) * 2 + ks) * 32 + lane) * 4) ^ (ks << 2)];
            *(uint4*)a[1] = *(const uint4*)&A[((((wm * 2 + 1) * 2 + ks) * 32 + lane) * 4) ^ (ks << 2)];
            #pragma unroll
            for (int na = 0; na < 4; na++) {
                int widx = ((((wn * 4 + na) * 2 + ks) * 32 + lane) * 2) ^ (ks << 1) ^ ldxor;
                *(uint2*)b[na] = *(const uint2*)&Bt[widx];
            }
            #pragma unroll
            for (int ma = 0; ma < 2; ma++)
                #pragma unroll
                for (int na = 0; na < 4; na++)
                    mma16(acc[ma][na], a[ma], b[na]);
        }
        if (it + 1 < 64) storeT(buf ^ 1);
        __syncthreads();
    }

    const int b = bh >> 3, h = bh & 7;
    float* oh = g_OH + ((long)b * N_ + rb * 128) * D_ + h * DH;
    #pragma unroll
    for (int ma = 0; ma < 2; ma++) {
        int row = wm * 32 + ma * 16 + (lane >> 2);
        #pragma unroll
        for (int na = 0; na < 4; na++) {
            int col = wn * 32 + na * 8 + (lane & 3) * 2;
            *(float2*)&oh[(long)row * D_ + col] =
                make_float2(acc[ma][na][0], acc[ma][na][1]);
            *(float2*)&oh[(long)(row + 8) * D_ + col] =
                make_float2(acc[ma][na][2], acc[ma][na][3]);
        }
    }
}

// ===========================================================================
// Kernel 5: Out = OutH @ Wo + bo via mma.sync tf32 (R13 verbatim)
// ===========================================================================
__global__ __launch_bounds__(256) void outproj_mma(
    const float* __restrict__ Wo, const float* __restrict__ bo,
    float* __restrict__ out)
{
    extern __shared__ float smf[];
    float* As = smf;
    float* Bs = smf + 2*128*APAD;

    const int tid = threadIdx.x, lane = tid & 31, wid = tid >> 5;
    const int wm = wid >> 1, wn = wid & 1;
    const int row0 = blockIdx.y * 128;
    const int col0 = blockIdx.x * 128;

    float4 ta[4]; float tb[16];
    auto loadA = [&](int k0) {
        #pragma unroll
        for (int q = 0; q < 4; q++) {
            int e = tid + q * 256;
            int r = e >> 3, kg = e & 7;
            ta[q] = *(const float4*)&g_OH[(long)(row0 + r) * D_ + k0 + kg * 4];
        }
    };
    auto loadB = [&](int k0) {
        #pragma unroll
        for (int j = 0; j < 16; j++) {
            int i = tid + j * 256;
            int k = i >> 7, n = i & 127;
            tb[j] = Wo[(long)(k0 + k) * D_ + col0 + n];
        }
    };
    auto stsA = [&](int buf) {
        float* Ab = As + buf * 128 * APAD;
        #pragma unroll
        for (int q = 0; q < 4; q++) {
            int e = tid + q * 256;
            int r = e >> 3, kg = e & 7;
            float4 v = ta[q];
            v.x = tf32r(v.x); v.y = tf32r(v.y); v.z = tf32r(v.z); v.w = tf32r(v.w);
            *(float4*)&Ab[r * APAD + kg * 4] = v;
        }
    };
    auto stsB = [&](int buf) {
        float* Bb = Bs + buf * 32 * BPAD;
        #pragma unroll
        for (int j = 0; j < 16; j++) {
            int i = tid + j * 256;
            int k = i >> 7, n = i & 127;
            Bb[k * BPAD + n] = tf32r(tb[j]);
        }
    };

    float acc[2][8][4] = {};
    loadA(0); loadB(0); stsA(0); stsB(0);
    __syncthreads();

    for (int c = 0; c < 16; c++) {
        if (c + 1 < 16) { loadA((c + 1) * 32); loadB((c + 1) * 32); }
        const int buf = c & 1;
        const float* Ab = As + buf * 128 * APAD;
        const float* Bb = Bs + buf * 32 * BPAD;

        #pragma unroll
        for (int ks = 0; ks < 4; ks++) {
            const int kk = ks * 8 + (lane & 3);
            uint32_t a[2][4], b[8][2];
            #pragma unroll
            for (int ma = 0; ma < 2; ma++) {
                int r = wm * 32 + ma * 16 + (lane >> 2);
                a[ma][0] = __float_as_uint(Ab[r * APAD + kk]);
                a[ma][1] = __float_as_uint(Ab[(r + 8) * APAD + kk]);
                a[ma][2] = __float_as_uint(Ab[r * APAD + kk + 4]);
                a[ma][3] = __float_as_uint(Ab[(r + 8) * APAD + kk + 4]);
            }
            #pragma unroll
            for (int na = 0; na < 8; na++) {
                int n = wn * 64 + na * 8 + (lane >> 2);
                b[na][0] = __float_as_uint(Bb[kk * BPAD + n]);
                b[na][1] = __float_as_uint(Bb[(kk + 4) * BPAD + n]);
            }
            #pragma unroll
            for (int ma = 0; ma < 2; ma++)
                #pragma unroll
                for (int na = 0; na < 8; na++)
                    mma8(acc[ma][na], a[ma], b[na]);
        }
        __syncthreads();
        if (c + 1 < 16) { stsA(buf ^ 1); stsB(buf ^ 1); }
        __syncthreads();
    }

    #pragma unroll
    for (int ma = 0; ma < 2; ma++) {
        #pragma unroll
        for (int half = 0; half < 2; half++) {
            int r = row0 + wm * 32 + ma * 16 + half * 8 + (lane >> 2);
            #pragma unroll
            for (int na = 0; na < 8; na++) {
                int cgl = col0 + wn * 64 + na * 8 + (lane & 3) * 2;
                float2 bias = *(const float2*)&bo[cgl];
                *(float2*)&out[(long)r * D_ + cgl] =
                    make_float2(acc[ma][na][half * 2 + 0] + bias.x,
                                acc[ma][na][half * 2 + 1] + bias.y);
            }
        }
    }
}

// ===========================================================================
extern "C" void kernel_launch(void* const* d_in, const int* in_sizes, int n_in,
                              void* d_out, int out_size)
{
    (void)in_sizes; (void)n_in; (void)out_size;
    const float* x   = (const float*)d_in[0];
    const float* met = (const float*)d_in[1];
    const float* yz  = (const float*)d_in[2];
    const float* Wq  = (const float*)d_in[3];
    const float* Wk  = (const float*)d_in[4];
    const float* Wv  = (const float*)d_in[5];
    const float* Wo  = (const float*)d_in[6];
    const float* bo  = (const float*)d_in[7];

    float* out  = (float*)d_out;                       // (4, 2048, 512)
    float* attn = out + (long)B_ * N_ * D_;            // (32, 2048, 2048)

    static int configured = 0;
    static cudaStream_t s2 = 0;
    static cudaEvent_t evFork = 0, evJoin = 0;
    if (!configured) {
        cudaFuncSetAttribute(proj_mma,    cudaFuncAttributeMaxDynamicSharedMemorySize, PROJ_SMEM);
        cudaFuncSetAttribute(sim_f16p,    cudaFuncAttributeMaxDynamicSharedMemorySize, SIM_SMEM);
        cudaFuncSetAttribute(pv_tc,       cudaFuncAttributeMaxDynamicSharedMemorySize, PV_SMEM);
        cudaFuncSetAttribute(outproj_mma, cudaFuncAttributeMaxDynamicSharedMemorySize, PROJ_SMEM);
        cudaStreamCreateWithFlags(&s2, cudaStreamNonBlocking);
        cudaEventCreateWithFlags(&evFork, cudaEventDisableTiming);
        cudaEventCreateWithFlags(&evJoin, cudaEventDisableTiming);
        configured = 1;
    }

    proj_mma<<<dim3(4, 64, 5), 256, PROJ_SMEM>>>(x, met, yz, Wq, Wk, Wv);
    sim_f16p<<<dim3(16, 32), 256, SIM_SMEM>>>();

    // fork: norm on s2 runs concurrently with pv+outproj on the main stream
    cudaEventRecord(evFork, 0);
    cudaStreamWaitEvent(s2, evFork, 0);
    norm_kernel<<<BHn * N_, 256, 0, s2>>>(attn);
    cudaEventRecord(evJoin, s2);

    pv_tc      <<<dim3(16, 32), 256, PV_SMEM>>>();
    outproj_mma<<<dim3(4, 64), 256, PROJ_SMEM>>>(Wo, bo, out);

    // join
    cudaStreamWaitEvent(0, evJoin, 0);
}

// round 17
// speedup vs baseline: 1.1564x; 1.1564x over previous
#include <cuda_runtime.h>
#include <cuda_fp16.h>
#include <math.h>
#include <cstdint>

#define B_   4
#define N_   2048
#define D_   512
#define H_   8
#define DH   64
#define DQ2  128          // concatenated head dim: [q | q_met]
#define BHn  (B_*H_)      // 32
#define ROWS (B_*N_)      // 8192
#define SCALE 0.125f      // 64^-0.5

// Scratch (device globals — no allocations allowed)
__device__ __half g_Q2h[BHn * N_ * DQ2];        // 16 MB [(bh), n, 128]
__device__ __half g_K2h[BHn * N_ * DQ2];        // 16 MB
__device__ __half g_Vth[BHn * DH * N_];         //  8 MB [(bh), d, n]
__device__ float  g_OH [ROWS * D_];             // 16 MB (b, n, h*64+d)
__device__ __half g_Ph [(long)BHn * N_ * N_];   // 268 MB unnormalized exp(sim)
__device__ float  g_RS [BHn * N_];              // 256 KB  1/rowsum

// ===========================================================================
// helpers
// ===========================================================================
__device__ __forceinline__ float tf32r(float x) {
    uint32_t u = __float_as_uint(x);
    asm("cvt.rn.tf32.f32 %0, %1;" : "=r"(u) : "r"(u));
    return __uint_as_float(u);
}
__device__ __forceinline__ uint32_t h2u(float a, float b) {
    __half2 h = __floats2half2_rn(a, b);
    return *(uint32_t*)&h;
}
__device__ __forceinline__ void mma8(float c[4], const uint32_t a[4], const uint32_t b[2]) {
    asm volatile(
        "mma.sync.aligned.m16n8k8.row.col.f32.tf32.tf32.f32 "
        "{%0,%1,%2,%3}, {%4,%5,%6,%7}, {%8,%9}, {%0,%1,%2,%3};"
        : "+f"(c[0]), "+f"(c[1]), "+f"(c[2]), "+f"(c[3])
        : "r"(a[0]), "r"(a[1]), "r"(a[2]), "r"(a[3]), "r"(b[0]), "r"(b[1]));
}
__device__ __forceinline__ void mma16(float c[4], const uint32_t a[4], const uint32_t b[2]) {
    asm volatile(
        "mma.sync.aligned.m16n8k16.row.col.f32.f16.f16.f32 "
        "{%0,%1,%2,%3}, {%4,%5,%6,%7}, {%8,%9}, {%0,%1,%2,%3};"
        : "+f"(c[0]), "+f"(c[1]), "+f"(c[2]), "+f"(c[3])
        : "r"(a[0]), "r"(a[1]), "r"(a[2]), "r"(a[3]), "r"(b[0]), "r"(b[1]));
}

// ===========================================================================
// Kernel 1: proj via mma.sync tf32; epilogue writes fp16 head-split tensors.
// (R13 verbatim)
// ===========================================================================
#define APAD 44
#define BPAD 136
#define PROJ_SMEM ((2*128*APAD + 2*32*BPAD) * 4)   // 79872 B

__global__ __launch_bounds__(256) void proj_mma(
    const float* __restrict__ x, const float* __restrict__ met,
    const float* __restrict__ yz, const float* __restrict__ Wq,
    const float* __restrict__ Wk, const float* __restrict__ Wv)
{
    extern __shared__ float smf[];
    float* As = smf;                    // 2 x [128][APAD]
    float* Bs = smf + 2*128*APAD;       // 2 x [32][BPAD]

    const int mode = blockIdx.z;
    const float* A = (mode == 0) ? x : (mode == 1 || mode == 3) ? met : yz;
    const float* W = (mode < 2) ? Wq : (mode < 4) ? Wk : Wv;

    const int tid = threadIdx.x, lane = tid & 31, wid = tid >> 5;
    const int wm = wid >> 1, wn = wid & 1;
    const int row0 = blockIdx.y * 128;
    const int col0 = blockIdx.x * 128;

    float4 ta[4]; float tb[16];
    auto loadA = [&](int k0) {
        #pragma unroll
        for (int q = 0; q < 4; q++) {
            int e = tid + q * 256;
            int r = e >> 3, kg = e & 7;
            ta[q] = *(const float4*)&A[(long)(row0 + r) * D_ + k0 + kg * 4];
        }
    };
    auto loadB = [&](int k0) {
        #pragma unroll
        for (int j = 0; j < 16; j++) {
            int i = tid + j * 256;
            int k = i >> 7, n = i & 127;
            tb[j] = W[(long)(k0 + k) * D_ + col0 + n];
        }
    };
    auto stsA = [&](int buf) {
        float* Ab = As + buf * 128 * APAD;
        #pragma unroll
        for (int q = 0; q < 4; q++) {
            int e = tid + q * 256;
            int r = e >> 3, kg = e & 7;
            float4 v = ta[q];
            v.x = tf32r(v.x); v.y = tf32r(v.y); v.z = tf32r(v.z); v.w = tf32r(v.w);
            *(float4*)&Ab[r * APAD + kg * 4] = v;
        }
    };
    auto stsB = [&](int buf) {
        float* Bb = Bs + buf * 32 * BPAD;
        #pragma unroll
        for (int j = 0; j < 16; j++) {
            int i = tid + j * 256;
            int k = i >> 7, n = i & 127;
            Bb[k * BPAD + n] = tf32r(tb[j]);
        }
    };

    float acc[2][8][4] = {};
    loadA(0); loadB(0); stsA(0); stsB(0);
    __syncthreads();

    for (int c = 0; c < 16; c++) {
        if (c + 1 < 16) { loadA((c + 1) * 32); loadB((c + 1) * 32); }
        const int buf = c & 1;
        const float* Ab = As + buf * 128 * APAD;
        const float* Bb = Bs + buf * 32 * BPAD;

        #pragma unroll
        for (int ks = 0; ks < 4; ks++) {
            const int kk = ks * 8 + (lane & 3);
            uint32_t a[2][4], b[8][2];
            #pragma unroll
            for (int ma = 0; ma < 2; ma++) {
                int r = wm * 32 + ma * 16 + (lane >> 2);
                a[ma][0] = __float_as_uint(Ab[r * APAD + kk]);
                a[ma][1] = __float_as_uint(Ab[(r + 8) * APAD + kk]);
                a[ma][2] = __float_as_uint(Ab[r * APAD + kk + 4]);
                a[ma][3] = __float_as_uint(Ab[(r + 8) * APAD + kk + 4]);
            }
            #pragma unroll
            for (int na = 0; na < 8; na++) {
                int n = wn * 64 + na * 8 + (lane >> 2);
                b[na][0] = __float_as_uint(Bb[kk * BPAD + n]);
                b[na][1] = __float_as_uint(Bb[(kk + 4) * BPAD + n]);
            }
            #pragma unroll
            for (int ma = 0; ma < 2; ma++)
                #pragma unroll
                for (int na = 0; na < 8; na++)
                    mma8(acc[ma][na], a[ma], b[na]);
        }
        __syncthreads();
        if (c + 1 < 16) { stsA(buf ^ 1); stsB(buf ^ 1); }
        __syncthreads();
    }

    #pragma unroll
    for (int ma = 0; ma < 2; ma++) {
        #pragma unroll
        for (int half = 0; half < 2; half++) {
            int r = row0 + wm * 32 + ma * 16 + half * 8 + (lane >> 2);
            int bb = r >> 11, n = r & 2047;
            #pragma unroll
            for (int na = 0; na < 8; na++) {
                int cgl = col0 + wn * 64 + na * 8 + (lane & 3) * 2;
                int h = cgl >> 6, d = cgl & 63;
                float p = acc[ma][na][half * 2 + 0];
                float q = acc[ma][na][half * 2 + 1];
                long base = (long)(bb * H_ + h) * N_ + n;
                if (mode == 0)
                    *(__half2*)&g_Q2h[base * DQ2 + d] = __floats2half2_rn(p, q);
                else if (mode == 1)
                    *(__half2*)&g_Q2h[base * DQ2 + d + DH] = __floats2half2_rn(p, q);
                else if (mode == 2)
                    *(__half2*)&g_K2h[base * DQ2 + d] = __floats2half2_rn(p, q);
                else if (mode == 3)
                    *(__half2*)&g_K2h[base * DQ2 + d + DH] = __floats2half2_rn(p, q);
                else {
                    g_Vth[((long)(bb * H_ + h) * DH + d) * N_ + n] = __float2half_rn(p);
                    g_Vth[((long)(bb * H_ + h) * DH + d + 1) * N_ + n] = __float2half_rn(q);
                }
            }
        }
    }
}

// ===========================================================================
// Kernel 2: sim via mma.sync fp16; epilogue writes p~ = exp(S*SCALE) fp16
// to g_Ph and accumulates rowsums -> g_RS.  (R13 verbatim)
// ===========================================================================
#define SIM_SMEM ((8192 + 2*2048 + 128) * 4)   // 49664 B

__global__ __launch_bounds__(256) void sim_f16p(void)
{
    extern __shared__ uint32_t sm[];
    uint32_t* Qs = sm;
    uint32_t* Kb = sm + 8192;
    float* rowsumS = (float*)(sm + 12288);

    const int tid = threadIdx.x, lane = tid & 31, wid = tid >> 5;
    const int wm = wid >> 1, wn = wid & 1;
    const int bh = blockIdx.y, rb = blockIdx.x;
    const __half* Qg = g_Q2h + ((long)bh * N_ + rb * 128) * DQ2;
    const __half* Kg = g_K2h + (long)bh * N_ * DQ2;
    __half* Php = g_Ph + ((long)bh * N_ + rb * 128) * N_;

    for (int e = tid; e < 8192; e += 256) {
        int j = e & 3, l = (e >> 2) & 31, ks = (e >> 7) & 7;
        int ma = (e >> 10) & 1, qm = (e >> 11) & 3;
        int r = qm * 32 + ma * 16 + (l >> 2) + (j & 1) * 8;
        int k = ks * 16 + (l & 3) * 2 + (j >> 1) * 8;
        Qs[e] = *(const uint32_t*)&Qg[(long)r * DQ2 + k];
    }
    if (tid < 128) rowsumS[tid] = 0.f;

    uint4 tk[2];
    auto loadK = [&](int it) {
        int ct = it >> 2, kc = it & 3;
        const __half* src = Kg + (long)(ct * 128) * DQ2 + kc * 32;
        #pragma unroll
        for (int q = 0; q < 2; q++) {
            int e = tid + q * 256;
            int col = e >> 2, kq = e & 3;
            tk[q] = *(const uint4*)(src + (long)col * DQ2 + kq * 8);
        }
    };
    auto storeK = [&](int buf) {
        uint32_t* Bb = Kb + buf * 2048;
        #pragma unroll
        for (int q = 0; q < 2; q++) {
            int e = tid + q * 256;
            int col = e >> 2, kq = e & 3;
            int wn_ = col >> 6, na = (col >> 3) & 7;
            int cb2 = (col >> 2) & 1;
            uint32_t w4[4] = { tk[q].x, tk[q].y, tk[q].z, tk[q].w };
            #pragma unroll
            for (int w = 0; w < 4; w++) {
                int k2 = kq * 8 + w * 2;
                int ks = k2 >> 4, kk2 = k2 & 15;
                int lt = ((col & 7) << 2) | ((kk2 >> 1) & 3);
                int reg = kk2 >> 3;
                int idx = ((((wn_ * 8 + na) * 2 + ks) * 32) + lt) * 2 + reg;
                idx ^= (ks << 1) ^ (cb2 << 2);
                Bb[idx] = w4[w];
            }
        }
    };

    float rs[2][2] = {};
    float acc[2][8][4];
    loadK(0); storeK(0);
    __syncthreads();

    const int ldxor = (((lane >> 4) & 1) << 2);
    for (int it = 0; it < 64; it++) {
        const int kc = it & 3, buf = it & 1;
        if (kc == 0) {
            #pragma unroll
            for (int i = 0; i < 2; i++)
                #pragma unroll
                for (int j = 0; j < 8; j++)
                    #pragma unroll
                    for (int t = 0; t < 4; t++) acc[i][j][t] = 0.f;
        }
        if (it + 1 < 64) loadK(it + 1);

        const uint32_t* Bb = Kb + buf * 2048;
        #pragma unroll
        for (int ks = 0; ks < 2; ks++) {
            int ksG = kc * 2 + ks;
            uint32_t a[2][4], b[8][2];
            *(uint4*)a[0] = *(const uint4*)&Qs[(((wm * 2 + 0) * 8 + ksG) * 32 + lane) * 4];
            *(uint4*)a[1] = *(const uint4*)&Qs[(((wm * 2 + 1) * 8 + ksG) * 32 + lane) * 4];
            #pragma unroll
            for (int na = 0; na < 8; na++) {
                int widx = ((((wn * 8 + na) * 2 + ks) * 32 + lane) * 2) ^ (ks << 1) ^ ldxor;
                *(uint2*)b[na] = *(const uint2*)&Bb[widx];
            }
            #pragma unroll
            for (int ma = 0; ma < 2; ma++)
                #pragma unroll
                for (int na = 0; na < 8; na++)
                    mma16(acc[ma][na], a[ma], b[na]);
        }

        if (kc == 3) {
            int ct = it >> 2;
            #pragma unroll
            for (int ma = 0; ma < 2; ma++) {
                int row = wm * 32 + ma * 16 + (lane >> 2);
                #pragma unroll
                for (int na = 0; na < 8; na++) {
                    float p0 = __expf(acc[ma][na][0] * SCALE);
                    float p1 = __expf(acc[ma][na][1] * SCALE);
                    float p2 = __expf(acc[ma][na][2] * SCALE);
                    float p3 = __expf(acc[ma][na][3] * SCALE);
                    rs[ma][0] += p0 + p1;
                    rs[ma][1] += p2 + p3;
                    int col = ct * 128 + wn * 64 + na * 8 + (lane & 3) * 2;
                    *(uint32_t*)&Php[(long)row * N_ + col]       = h2u(p0, p1);
                    *(uint32_t*)&Php[(long)(row + 8) * N_ + col] = h2u(p2, p3);
                }
            }
        }
        if (it + 1 < 64) storeK(buf ^ 1);
        __syncthreads();
    }

    #pragma unroll
    for (int ma = 0; ma < 2; ma++)
        #pragma unroll
        for (int hf = 0; hf < 2; hf++) {
            float v = rs[ma][hf];
            v += __shfl_xor_sync(0xffffffffu, v, 1);
            v += __shfl_xor_sync(0xffffffffu, v, 2);
            if ((lane & 3) == 0)
                atomicAdd(&rowsumS[wm * 32 + ma * 16 + hf * 8 + (lane >> 2)], v);
        }
    __syncthreads();
    if (tid < 128)
        g_RS[bh * N_ + rb * 128 + tid] = 1.0f / rowsumS[tid];
}

// ===========================================================================
// Kernel 3: normalize — attn = float(p~) * (1/rowsum).  (R13 verbatim)
// ===========================================================================
__global__ __launch_bounds__(256) void norm_kernel(float* __restrict__ attn)
{
    const long row = blockIdx.x;
    const __half* p = g_Ph + row * N_;
    float* o = attn + row * N_;
    const float iv = g_RS[row];
    const int c8 = threadIdx.x * 8;
    uint4 v = *(const uint4*)&p[c8];
    __half2* hp = (__half2*)&v;
    float2 f0 = __half22float2(hp[0]);
    float2 f1 = __half22float2(hp[1]);
    float2 f2 = __half22float2(hp[2]);
    float2 f3 = __half22float2(hp[3]);
    *(float4*)&o[c8]     = make_float4(f0.x * iv, f0.y * iv, f1.x * iv, f1.y * iv);
    *(float4*)&o[c8 + 4] = make_float4(f2.x * iv, f2.y * iv, f3.x * iv, f3.y * iv);
}

// ===========================================================================
// Kernel 4: OutH = attn @ V via fp16 mma; A = p~ * (1/rowsum).
// 64-k chunks: 32 iterations, 32 MMAs per stage, half the syncs of R13.
// ===========================================================================
#define PV_SMEM ((2*4096 + 2*2048 + 128) * 4)   // 49664 B

__global__ __launch_bounds__(256) void pv_tc(void)
{
    extern __shared__ uint32_t sm[];
    uint32_t* Ab = sm;            // 2 x 4096 words: A frags (swizzled)
    uint32_t* Bv = sm + 8192;     // 2 x 2048 words: V frags (swizzled)
    float* sInv = (float*)(sm + 12288);

    const int tid = threadIdx.x, lane = tid & 31, wid = tid >> 5;
    const int wm = wid >> 1, wn = wid & 1;
    const int bh = blockIdx.y, rb = blockIdx.x;
    const __half* Pg = g_Ph + ((long)bh * N_ + rb * 128) * N_;
    const __half* Vg = g_Vth + (long)bh * DH * N_;

    if (tid < 128) sInv[tid] = g_RS[bh * N_ + rb * 128 + tid];
    __syncthreads();

    uint4 tph[4]; uint4 tv[2];
    auto loadT = [&](int it) {            // it = 64-k chunk index (0..31)
        #pragma unroll
        for (int q = 0; q < 4; q++) {
            int e = tid + q * 256;
            int row = e >> 3, kq = e & 7;
            tph[q] = *(const uint4*)(Pg + (long)row * N_ + it * 64 + kq * 8);
        }
        #pragma unroll
        for (int q = 0; q < 2; q++) {
            int e = tid + q * 256;
            int d = e >> 3, kq = e & 7;
            tv[q] = *(const uint4*)(Vg + (long)d * N_ + it * 64 + kq * 8);
        }
    };
    auto storeT = [&](int buf) {
        uint32_t* A = Ab + buf * 4096;
        #pragma unroll
        for (int q = 0; q < 4; q++) {
            int e = tid + q * 256;
            int row = e >> 3, kq = e & 7;
            float iv = sInv[row];
            int wm_ = row >> 5, ma = (row >> 4) & 1, rr = row & 15;
            const __half2* hp = (const __half2*)&tph[q];
            #pragma unroll
            for (int w = 0; w < 4; w++) {
                float2 f = __half22float2(hp[w]);
                int k2 = kq * 8 + w * 2;          // 0..62
                int ks = k2 >> 4, kk2 = k2 & 15;  // ks 0..3
                int lt = ((rr & 7) << 2) | ((kk2 >> 1) & 3);
                int j = (rr >> 3) | ((kk2 >> 3) << 1);
                int idx = (((((wm_ * 2 + ma) * 4 + ks) * 32) + lt) * 4 + j) ^ (ks << 2);
                A[idx] = h2u(f.x * iv, f.y * iv);
            }
        }
        uint32_t* Bt = Bv + buf * 2048;
        #pragma unroll
        for (int q = 0; q < 2; q++) {
            int e = tid + q * 256;
            int d = e >> 3, kq = e & 7;
            int wn_ = d >> 5, na = (d >> 3) & 3;
            int cb2 = (d >> 2) & 1;
            uint32_t w4[4] = { tv[q].x, tv[q].y, tv[q].z, tv[q].w };
            #pragma unroll
            for (int w = 0; w < 4; w++) {
                int k2 = kq * 8 + w * 2;
                int ks = k2 >> 4, kk2 = k2 & 15;
                int lt = ((d & 7) << 2) | ((kk2 >> 1) & 3);
                int reg = kk2 >> 3;
                int idx = ((((wn_ * 4 + na) * 4 + ks) * 32) + lt) * 2 + reg;
                idx ^= (ks << 1) ^ (cb2 << 2);
                Bt[idx] = w4[w];
            }
        }
    };

    float acc[2][4][4] = {};
    loadT(0); storeT(0);
    __syncthreads();

    const int ldxor = (((lane >> 4) & 1) << 2);
    for (int it = 0; it < 32; it++) {
        const int buf = it & 1;
        if (it + 1 < 32) loadT(it + 1);

        const uint32_t* A = Ab + buf * 4096;
        const uint32_t* Bt = Bv + buf * 2048;
        #pragma unroll
        for (int ks = 0; ks < 4; ks++) {
            uint32_t a[2][4], b[4][2];
            *(uint4*)a[0] = *(const uint4*)&A[((((wm * 2 + 0) * 4 + ks) * 32 + lane) * 4) ^ (ks << 2)];
            *(uint4*)a[1] = *(const uint4*)&A[((((wm * 2 + 1) * 4 + ks) * 32 + lane) * 4) ^ (ks << 2)];
            #pragma unroll
            for (int na = 0; na < 4; na++) {
                int widx = ((((wn * 4 + na) * 4 + ks) * 32 + lane) * 2) ^ (ks << 1) ^ ldxor;
                *(uint2*)b[na] = *(const uint2*)&Bt[widx];
            }
            #pragma unroll
            for (int ma = 0; ma < 2; ma++)
                #pragma unroll
                for (int na = 0; na < 4; na++)
                    mma16(acc[ma][na], a[ma], b[na]);
        }
        if (it + 1 < 32) storeT(buf ^ 1);
        __syncthreads();
    }

    const int b = bh >> 3, h = bh & 7;
    float* oh = g_OH + ((long)b * N_ + rb * 128) * D_ + h * DH;
    #pragma unroll
    for (int ma = 0; ma < 2; ma++) {
        int row = wm * 32 + ma * 16 + (lane >> 2);
        #pragma unroll
        for (int na = 0; na < 4; na++) {
            int col = wn * 32 + na * 8 + (lane & 3) * 2;
            *(float2*)&oh[(long)row * D_ + col] =
                make_float2(acc[ma][na][0], acc[ma][na][1]);
            *(float2*)&oh[(long)(row + 8) * D_ + col] =
                make_float2(acc[ma][na][2], acc[ma][na][3]);
        }
    }
}

// ===========================================================================
// Kernel 5: Out = OutH @ Wo + bo via mma.sync tf32 (R13 verbatim)
// ===========================================================================
__global__ __launch_bounds__(256) void outproj_mma(
    const float* __restrict__ Wo, const float* __restrict__ bo,
    float* __restrict__ out)
{
    extern __shared__ float smf[];
    float* As = smf;
    float* Bs = smf + 2*128*APAD;

    const int tid = threadIdx.x, lane = tid & 31, wid = tid >> 5;
    const int wm = wid >> 1, wn = wid & 1;
    const int row0 = blockIdx.y * 128;
    const int col0 = blockIdx.x * 128;

    float4 ta[4]; float tb[16];
    auto loadA = [&](int k0) {
        #pragma unroll
        for (int q = 0; q < 4; q++) {
            int e = tid + q * 256;
            int r = e >> 3, kg = e & 7;
            ta[q] = *(const float4*)&g_OH[(long)(row0 + r) * D_ + k0 + kg * 4];
        }
    };
    auto loadB = [&](int k0) {
        #pragma unroll
        for (int j = 0; j < 16; j++) {
            int i = tid + j * 256;
            int k = i >> 7, n = i & 127;
            tb[j] = Wo[(long)(k0 + k) * D_ + col0 + n];
        }
    };
    auto stsA = [&](int buf) {
        float* Ab = As + buf * 128 * APAD;
        #pragma unroll
        for (int q = 0; q < 4; q++) {
            int e = tid + q * 256;
            int r = e >> 3, kg = e & 7;
            float4 v = ta[q];
            v.x = tf32r(v.x); v.y = tf32r(v.y); v.z = tf32r(v.z); v.w = tf32r(v.w);
            *(float4*)&Ab[r * APAD + kg * 4] = v;
        }
    };
    auto stsB = [&](int buf) {
        float* Bb = Bs + buf * 32 * BPAD;
        #pragma unroll
        for (int j = 0; j < 16; j++) {
            int i = tid + j * 256;
            int k = i >> 7, n = i & 127;
            Bb[k * BPAD + n] = tf32r(tb[j]);
        }
    };

    float acc[2][8][4] = {};
    loadA(0); loadB(0); stsA(0); stsB(0);
    __syncthreads();

    for (int c = 0; c < 16; c++) {
        if (c + 1 < 16) { loadA((c + 1) * 32); loadB((c + 1) * 32); }
        const int buf = c & 1;
        const float* Ab = As + buf * 128 * APAD;
        const float* Bb = Bs + buf * 32 * BPAD;

        #pragma unroll
        for (int ks = 0; ks < 4; ks++) {
            const int kk = ks * 8 + (lane & 3);
            uint32_t a[2][4], b[8][2];
            #pragma unroll
            for (int ma = 0; ma < 2; ma++) {
                int r = wm * 32 + ma * 16 + (lane >> 2);
                a[ma][0] = __float_as_uint(Ab[r * APAD + kk]);
                a[ma][1] = __float_as_uint(Ab[(r + 8) * APAD + kk]);
                a[ma][2] = __float_as_uint(Ab[r * APAD + kk + 4]);
                a[ma][3] = __float_as_uint(Ab[(r + 8) * APAD + kk + 4]);
            }
            #pragma unroll
            for (int na = 0; na < 8; na++) {
                int n = wn * 64 + na * 8 + (lane >> 2);
                b[na][0] = __float_as_uint(Bb[kk * BPAD + n]);
                b[na][1] = __float_as_uint(Bb[(kk + 4) * BPAD + n]);
            }
            #pragma unroll
            for (int ma = 0; ma < 2; ma++)
                #pragma unroll
                for (int na = 0; na < 8; na++)
                    mma8(acc[ma][na], a[ma], b[na]);
        }
        __syncthreads();
        if (c + 1 < 16) { stsA(buf ^ 1); stsB(buf ^ 1); }
        __syncthreads();
    }

    #pragma unroll
    for (int ma = 0; ma < 2; ma++) {
        #pragma unroll
        for (int half = 0; half < 2; half++) {
            int r = row0 + wm * 32 + ma * 16 + half * 8 + (lane >> 2);
            #pragma unroll
            for (int na = 0; na < 8; na++) {
                int cgl = col0 + wn * 64 + na * 8 + (lane & 3) * 2;
                float2 bias = *(const float2*)&bo[cgl];
                *(float2*)&out[(long)r * D_ + cgl] =
                    make_float2(acc[ma][na][half * 2 + 0] + bias.x,
                                acc[ma][na][half * 2 + 1] + bias.y);
            }
        }
    }
}

// ===========================================================================
extern "C" void kernel_launch(void* const* d_in, const int* in_sizes, int n_in,
                              void* d_out, int out_size)
{
    (void)in_sizes; (void)n_in; (void)out_size;
    const float* x   = (const float*)d_in[0];
    const float* met = (const float*)d_in[1];
    const float* yz  = (const float*)d_in[2];
    const float* Wq  = (const float*)d_in[3];
    const float* Wk  = (const float*)d_in[4];
    const float* Wv  = (const float*)d_in[5];
    const float* Wo  = (const float*)d_in[6];
    const float* bo  = (const float*)d_in[7];

    float* out  = (float*)d_out;                       // (4, 2048, 512)
    float* attn = out + (long)B_ * N_ * D_;            // (32, 2048, 2048)

    static int configured = 0;
    static cudaStream_t s2 = 0;
    static cudaEvent_t evFork = 0, evJoin = 0;
    if (!configured) {
        cudaFuncSetAttribute(proj_mma,    cudaFuncAttributeMaxDynamicSharedMemorySize, PROJ_SMEM);
        cudaFuncSetAttribute(sim_f16p,    cudaFuncAttributeMaxDynamicSharedMemorySize, SIM_SMEM);
        cudaFuncSetAttribute(pv_tc,       cudaFuncAttributeMaxDynamicSharedMemorySize, PV_SMEM);
        cudaFuncSetAttribute(outproj_mma, cudaFuncAttributeMaxDynamicSharedMemorySize, PROJ_SMEM);
        cudaStreamCreateWithFlags(&s2, cudaStreamNonBlocking);
        cudaEventCreateWithFlags(&evFork, cudaEventDisableTiming);
        cudaEventCreateWithFlags(&evJoin, cudaEventDisableTiming);
        configured = 1;
    }

    proj_mma<<<dim3(4, 64, 5), 256, PROJ_SMEM>>>(x, met, yz, Wq, Wk, Wv);
    sim_f16p<<<dim3(16, 32), 256, SIM_SMEM>>>();
    pv_tc   <<<dim3(16, 32), 256, PV_SMEM>>>();

    // fork AFTER pv: norm (DRAM-bound) runs concurrently with outproj
    // (tensor-bound, DRAM ~5%) — disjoint bottlenecks.
    cudaEventRecord(evFork, 0);
    cudaStreamWaitEvent(s2, evFork, 0);
    norm_kernel<<<BHn * N_, 256, 0, s2>>>(attn);
    cudaEventRecord(evJoin, s2);

    outproj_mma<<<dim3(4, 64), 256, PROJ_SMEM>>>(Wo, bo, out);

    cudaStreamWaitEvent(0, evJoin, 0);
}